// round 15
// baseline (speedup 1.0000x reference)
#include <cuda_runtime.h>
#include <cuda_fp16.h>
#include <cstdint>

// ---------------------------------------------------------------------------
// SparseGaussianHead: two sparse-conv layers (27-offset gather-GEMM) + GELU
//   L1: [400k x 64] -> [400k x 38]   (N padded to 40)
//   L2: [400k x 38] -> [400k x 38]   (K padded to 48, N padded to 40)
// fp16 m16n8k16 MMA, fp32 accumulate. Zero smem, zero barriers.
// R11: R10 design (64 rows/warp = 4 m16 tiles, B amortized 4x, LDG.128
//      B packing) with the host->__device__-symbol bug fixed: weight pack
//      kernel selects its output arrays via template, never via host pointer.
// ---------------------------------------------------------------------------

#define NPTS 400000
#define NOFF 27

__device__ __half g_feat[(NPTS + 1) * 64];    // permuted fp16 features + zero pad row
__device__ __half g_h[(NPTS + 1) * 48];       // permuted gelu out + zero pad row
// packed B fragments: q = [k][kk][pair][lane] uint4 (j=0,1 / j=2,3),
//                     r = [k][kk][lane] uint2 (j=4)
__device__ uint4 g_W1q[NOFF * 4 * 2 * 32];
__device__ uint2 g_W1r[NOFF * 4 * 32];
__device__ uint4 g_W2q[NOFF * 3 * 2 * 32];
__device__ uint2 g_W2r[NOFF * 3 * 32];

__device__ __forceinline__ float gelu_exact(float x) {
    return 0.5f * x * (1.0f + erff(x * 0.7071067811865476f));
}

// per-16-column-chunk permutation: logical col c -> storage position.
// Puts cols (2t, 2t+1, 2t+8, 2t+9) at positions (4t, 4t+1, 4t+2, 4t+3).
__device__ __forceinline__ int perm16(int c) {
    int q = c & ~15, r = c & 15;
    int pos = (r < 8) ? ((r >> 1) * 4 + (r & 1))
                      : (((r - 8) >> 1) * 4 + 2 + (r & 1));
    return q | pos;
}

// ------------------------------ prep kernels ------------------------------

__global__ void prep_feat(const float* __restrict__ F) {
    int e = blockIdx.x * 256 + threadIdx.x;
    if (e < NPTS * 64) {
        int row = e >> 6, c = e & 63;
        g_feat[row * 64 + perm16(c)] = __float2half_rn(F[e]);
    } else if (e < (NPTS + 1) * 64) {
        g_feat[e] = __float2half_rn(0.0f);          // pad row
    }
    if (e < 48)
        g_h[(size_t)NPTS * 48 + e] = __float2half_rn(0.0f);  // pad row of g_h
}

// Pack W into q/r fragment arrays. LAYER selects the __device__ destinations
// INSIDE device code (host code must never take a __device__ symbol address).
template <int LAYER>
__global__ void prep_wf(const float* __restrict__ W) {
    constexpr int CIN = (LAYER == 1) ? 64 : 38;
    constexpr int KK  = (LAYER == 1) ? 4 : 3;
    uint4* __restrict__ Wq = (LAYER == 1) ? g_W1q : g_W2q;
    uint2* __restrict__ Wr = (LAYER == 1) ? g_W1r : g_W2r;

    int e = blockIdx.x * 256 + threadIdx.x;
    if (e >= NOFF * KK * 32) return;
    int lane = e & 31;
    int r = e >> 5;
    int kk = r % KK;
    int k = r / KK;
    int g = lane >> 2, t = lane & 3;
    int c = 16 * kk + 2 * t;
    auto wv = [&](int n, int cc) -> float {
        return (n < 38 && cc < CIN) ? W[((size_t)k * CIN + cc) * 38 + n] : 0.0f;
    };
    unsigned b[5][2];
#pragma unroll
    for (int j = 0; j < 5; j++) {
        int n = j * 8 + g;
        __half2 h0 = __floats2half2_rn(wv(n, c), wv(n, c + 1));
        __half2 h1 = __floats2half2_rn(wv(n, c + 8), wv(n, c + 9));
        b[j][0] = *(unsigned*)&h0;
        b[j][1] = *(unsigned*)&h1;
    }
    Wq[((k * KK + kk) * 2 + 0) * 32 + lane] =
        make_uint4(b[0][0], b[0][1], b[1][0], b[1][1]);
    Wq[((k * KK + kk) * 2 + 1) * 32 + lane] =
        make_uint4(b[2][0], b[2][1], b[3][0], b[3][1]);
    Wr[(k * KK + kk) * 32 + lane] = make_uint2(b[4][0], b[4][1]);
}

// ------------------------------ conv kernel -------------------------------
// 128 threads = 4 warps; CTA = 256 rows; warp owns 64 rows = four m16 tiles.
// All operands LDG'd straight into fragment registers; invalid/out-of-range
// rows read the zero pad row (idx == NPTS). Grid is ragged (last CTA 128 rows).
// MODE 0: in g_feat (KD=64), out g_h (exact GELU, fp16, permuted cols)
// MODE 1: in g_h    (KD=48), out d_out (first 38 cols, fp32)

template <int KD, int MODE>
__global__ __launch_bounds__(128) void conv_r(const int* __restrict__ nbr,
                                              float* __restrict__ dout) {
    constexpr int KK = KD / 16;           // 4 / 3
    const __half* __restrict__ feat = (MODE == 0) ? g_feat : g_h;
    const uint4* __restrict__ Wq    = (MODE == 0) ? g_W1q  : g_W2q;
    const uint2* __restrict__ Wr    = (MODE == 0) ? g_W1r  : g_W2r;

    const int tid  = threadIdx.x;
    const int warp = tid >> 5;
    const int lane = tid & 31;
    const int g    = lane >> 2;   // 0..7
    const int t    = lane & 3;    // 0..3
    const int base = blockIdx.x * 256 + warp * 64;

    float acc[4][5][4];
#pragma unroll
    for (int tt = 0; tt < 4; tt++)
#pragma unroll
        for (int j = 0; j < 5; j++)
#pragma unroll
            for (int q = 0; q < 4; q++) acc[tt][j][q] = 0.0f;

    for (int k = 0; k < NOFF; k++) {
        const int* nk = nbr + k * NPTS + base;
        // 8 fragment row indices; out-of-range/invalid -> pad row NPTS
        int idx[8];
#pragma unroll
        for (int m = 0; m < 8; m++) {
            const int grow = base + g + 8 * m;
            idx[m] = NPTS;
            if (grow < NPTS) idx[m] = __ldg(nk + g + 8 * m);
        }
        const uint2* rp[8];
#pragma unroll
        for (int m = 0; m < 8; m++)
            rp[m] = (const uint2*)(feat + (size_t)idx[m] * KD) + t;

        const uint4* wq = Wq + k * (KK * 2 * 32) + lane;
        const uint2* wr = Wr + k * (KK * 32) + lane;

#pragma unroll
        for (int kk = 0; kk < KK; ++kk) {
            uint2 v[8];
#pragma unroll
            for (int m = 0; m < 8; m++)
                v[m] = __ldg(rp[m] + kk * 4);
            const uint4 q0 = __ldg(wq + (kk * 2 + 0) * 32);
            const uint4 q1 = __ldg(wq + (kk * 2 + 1) * 32);
            const uint2 r2 = __ldg(wr + kk * 32);
            const unsigned bf[5][2] = {{q0.x, q0.y}, {q0.z, q0.w},
                                       {q1.x, q1.y}, {q1.z, q1.w},
                                       {r2.x, r2.y}};
#pragma unroll
            for (int j = 0; j < 5; j++) {
#pragma unroll
                for (int tt = 0; tt < 4; tt++) {
                    asm volatile(
                        "mma.sync.aligned.m16n8k16.row.col.f32.f16.f16.f32 "
                        "{%0,%1,%2,%3}, {%4,%5,%6,%7}, {%8,%9}, {%0,%1,%2,%3};\n"
                        : "+f"(acc[tt][j][0]), "+f"(acc[tt][j][1]),
                          "+f"(acc[tt][j][2]), "+f"(acc[tt][j][3])
                        : "r"(v[2 * tt].x), "r"(v[2 * tt + 1].x),
                          "r"(v[2 * tt].y), "r"(v[2 * tt + 1].y),
                          "r"(bf[j][0]), "r"(bf[j][1]));
                }
            }
        }
    }

    // --- epilogue (guard ragged last CTA) ---
#pragma unroll
    for (int tt = 0; tt < 4; tt++) {
        const int r0 = base + tt * 16 + g;
#pragma unroll
        for (int j = 0; j < 5; j++) {
            const int c0 = j * 8 + 2 * t;
            if (MODE == 0) {
                const int pc = perm16(c0);   // pair (c0, c0+1) stays adjacent
                if (r0 < NPTS)
                    *(__half2*)&g_h[(size_t)r0 * 48 + pc] =
                        __floats2half2_rn(gelu_exact(acc[tt][j][0]),
                                          gelu_exact(acc[tt][j][1]));
                if (r0 + 8 < NPTS)
                    *(__half2*)&g_h[(size_t)(r0 + 8) * 48 + pc] =
                        __floats2half2_rn(gelu_exact(acc[tt][j][2]),
                                          gelu_exact(acc[tt][j][3]));
            } else {
                if (r0 < NPTS) {
                    if (c0 < 38)     dout[(size_t)r0 * 38 + c0]     = acc[tt][j][0];
                    if (c0 + 1 < 38) dout[(size_t)r0 * 38 + c0 + 1] = acc[tt][j][1];
                }
                if (r0 + 8 < NPTS) {
                    if (c0 < 38)     dout[(size_t)(r0 + 8) * 38 + c0]     = acc[tt][j][2];
                    if (c0 + 1 < 38) dout[(size_t)(r0 + 8) * 38 + c0 + 1] = acc[tt][j][3];
                }
            }
        }
        if (MODE == 0) {
            // zero logical cols 40..47 = permuted chunk-2 positions 4t+2,4t+3
            const __half2 z = __floats2half2_rn(0.f, 0.f);
            const int pz = 32 + 4 * t + 2;
            if (r0 < NPTS)     *(__half2*)&g_h[(size_t)r0 * 48 + pz]       = z;
            if (r0 + 8 < NPTS) *(__half2*)&g_h[(size_t)(r0 + 8) * 48 + pz] = z;
        }
    }
}

// ------------------------------ launch ------------------------------------

extern "C" void kernel_launch(void* const* d_in, const int* in_sizes, int n_in,
                              void* d_out, int out_size) {
    const float* F   = (const float*)d_in[0];   // [400000, 64]
    const int*   nbr = (const int*)d_in[1];     // [27, 400000]
    const float* W1  = (const float*)d_in[2];   // [27, 64, 38]
    const float* W2  = (const float*)d_in[3];   // [27, 38, 38]
    float* out = (float*)d_out;                 // [400000, 38]

    prep_feat<<<((NPTS + 1) * 64 + 255) / 256, 256>>>(F);
    prep_wf<1><<<(NOFF * 4 * 32 + 255) / 256, 256>>>(W1);
    prep_wf<2><<<(NOFF * 3 * 32 + 255) / 256, 256>>>(W2);

    const int grid = (NPTS + 255) / 256;        // 1563, last CTA ragged
    conv_r<64, 0><<<grid, 128>>>(nbr, nullptr); // L1 + GELU -> g_h
    conv_r<48, 1><<<grid, 128>>>(nbr, out);     // L2 -> d_out
}